// round 4
// baseline (speedup 1.0000x reference)
#include <cuda_runtime.h>
#include <cuda_fp16.h>
#include <math.h>

#define BATCH 4
#define CH    128
#define N_    4096
#define EPSV  2.220446049250313e-16f
#define SCALE2 144.26950408889634f   // 100 * log2(e)

// ---------------------------------------------------------------------------
// Device scratch
// ---------------------------------------------------------------------------
__device__ float g_xbar[2 * BATCH * CH];
__device__ float g_theta[BATCH * CH * N_];        // keys    [b][c][m]
__device__ float g_phi[BATCH * CH * N_];          // queries [b][c][n]
__device__ float g_rsT[BATCH * N_ * CH];          // values  [b][m][c]
__device__ float g_Qh [BATCH * 32 * 16384];       // Q hi, A-fragment order per 128-row block
__device__ unsigned int g_Qlo[BATCH * 32 * 8192]; // Q lo (half2 pairs), same order
__device__ float g_Kpk[BATCH * 64 * 16384];       // K packed (b0h,b1h,b0l,b1l) per 64-key block

__device__ __forceinline__ unsigned int f2tf32(float x) {
    unsigned int r;
    asm("cvt.rna.tf32.f32 %0, %1;" : "=r"(r) : "f"(x));
    return r;
}

__device__ __forceinline__ void mma_tf32(float c[4],
                                         unsigned int a0, unsigned int a1,
                                         unsigned int a2, unsigned int a3,
                                         unsigned int b0, unsigned int b1) {
    asm volatile("mma.sync.aligned.m16n8k8.row.col.f32.tf32.tf32.f32 "
                 "{%0,%1,%2,%3}, {%4,%5,%6,%7}, {%8,%9}, {%0,%1,%2,%3};\n"
                 : "+f"(c[0]), "+f"(c[1]), "+f"(c[2]), "+f"(c[3])
                 : "r"(a0), "r"(a1), "r"(a2), "r"(a3), "r"(b0), "r"(b1));
}

// ---------------------------------------------------------------------------
// K0: spatial means
// ---------------------------------------------------------------------------
__global__ void k_means(const float* __restrict__ m_in, const float* __restrict__ rs) {
    int row   = blockIdx.x;
    int which = row >> 9;
    int bc    = row & 511;
    const float* src = which ? m_in : rs;
    const float* p = src + (size_t)bc * N_;

    float s = 0.f;
    for (int i = threadIdx.x; i < N_; i += 256) s += p[i];

    __shared__ float sh[256];
    sh[threadIdx.x] = s;
    __syncthreads();
    for (int off = 128; off > 0; off >>= 1) {
        if (threadIdx.x < off) sh[threadIdx.x] += sh[threadIdx.x + off];
        __syncthreads();
    }
    if (threadIdx.x == 0) g_xbar[which * 512 + bc] = sh[0] * (1.0f / N_);
}

// ---------------------------------------------------------------------------
// K1: projection + mean-center + L2-normalize (bias cancels under centering)
// ---------------------------------------------------------------------------
__global__ void k_proj(const float* __restrict__ m_in, const float* __restrict__ rs,
                       const float* __restrict__ theta_w, const float* __restrict__ phi_w) {
    int tile  = blockIdx.x;
    int b     = blockIdx.y;
    int which = blockIdx.z;
    const float* X = which ? m_in : rs;
    const float* W = which ? phi_w : theta_w;
    float* OUT     = which ? g_phi : g_theta;
    const float* xbar = &g_xbar[which * 512 + b * CH];

    int o  = threadIdx.x;
    int n0 = tile * 16;

    __shared__ float Ws[128 * 33];
    __shared__ float xs[32 * 16];
    __shared__ float sq[128 * 17];

    float acc[16];
#pragma unroll
    for (int j = 0; j < 16; j++) acc[j] = 0.f;

    for (int c0 = 0; c0 < CH; c0 += 32) {
        for (int i = threadIdx.x; i < 128 * 32; i += 128) {
            int oo = i >> 5, cc = i & 31;
            Ws[oo * 33 + cc] = W[oo * CH + c0 + cc];
        }
        for (int i = threadIdx.x; i < 32 * 16; i += 128) {
            int cc = i >> 4;
            int j  = i & 15;
            int c  = c0 + cc;
            xs[i] = X[((size_t)(b * CH + c)) * N_ + n0 + j] - xbar[c];
        }
        __syncthreads();
#pragma unroll 8
        for (int cc = 0; cc < 32; cc++) {
            float w = Ws[o * 33 + cc];
#pragma unroll
            for (int j = 0; j < 16; j++) acc[j] += w * xs[cc * 16 + j];
        }
        __syncthreads();
    }

#pragma unroll
    for (int j = 0; j < 16; j++) sq[o * 17 + j] = acc[j] * acc[j];
    for (int off = 64; off > 0; off >>= 1) {
        __syncthreads();
        if (o < off) {
#pragma unroll
            for (int j = 0; j < 16; j++) sq[o * 17 + j] += sq[(o + off) * 17 + j];
        }
    }
    __syncthreads();

#pragma unroll
    for (int j = 0; j < 16; j++) {
        float norm = sqrtf(sq[j]) + EPSV;
        OUT[((size_t)(b * CH + o)) * N_ + n0 + j] = acc[j] / norm;
    }
}

// ---------------------------------------------------------------------------
// K1b: transpose rs -> g_rsT[b][n][c]
// ---------------------------------------------------------------------------
__global__ void k_transpose(const float* __restrict__ rs) {
    __shared__ float t[32][33];
    int n0 = blockIdx.x << 5;
    int c0 = blockIdx.y << 5;
    int b  = blockIdx.z;
    int tx = threadIdx.x, tyy = threadIdx.y;
    for (int r = tyy; r < 32; r += 8)
        t[r][tx] = rs[((size_t)(b * CH + c0 + r)) * N_ + n0 + tx];
    __syncthreads();
    for (int nn = tyy; nn < 32; nn += 8)
        g_rsT[((size_t)(b * N_ + n0 + nn)) * CH + c0 + tx] = t[tx][nn];
}

// ---------------------------------------------------------------------------
// Pack Q (phi) into m16n8k8 A-fragment order: hi fp32(tf32) + lo f16.
// idx = ((ks*8+mt)*32+lane)*4 + j, j = (colhalf<<1)|rowhalf.
// grid (32, BATCH), 256 threads.
// ---------------------------------------------------------------------------
__global__ void k_packQ() {
    extern __shared__ char psm[];
    float*  hi_s = (float*)psm;                  // 16384 floats
    __half* lo_s = (__half*)(psm + 65536);       // 16384 halves
    int blk = blockIdx.x, b = blockIdx.y;
    int n0 = blk * 128;

    for (int i = threadIdx.x; i < 16384; i += 256) {
        int r = i & 127, c = i >> 7;
        float v = g_phi[((size_t)(b * CH + c)) * N_ + n0 + r];
        float hf = __uint_as_float(f2tf32(v));
        float lo = v - hf;
        int rr = r & 15, mt = r >> 4, g = rr & 7, hb = rr >> 3;
        int cc = c & 7,  ks = c >> 3, l = cc & 3, ch = cc >> 2;
        int lane = (g << 2) | l;
        int j    = (ch << 1) | hb;
        int idx  = ((ks * 8 + mt) * 32 + lane) * 4 + j;
        hi_s[idx] = hf;
        lo_s[idx] = __float2half(lo);
    }
    __syncthreads();

    float4* hod = (float4*)(g_Qh + ((size_t)(b * 32 + blk)) * 16384);
    const float4* his = (const float4*)hi_s;
    for (int i = threadIdx.x; i < 4096; i += 256) hod[i] = his[i];

    uint4* lod = (uint4*)(g_Qlo + ((size_t)(b * 32 + blk)) * 8192);
    const uint4* los = (const uint4*)lo_s;
    for (int i = threadIdx.x; i < 2048; i += 256) lod[i] = los[i];
}

// ---------------------------------------------------------------------------
// Pack K (theta) into B-fragment order: float4 = (b0h, b1h, b0l, b1l).
// grid (64, BATCH), 256 threads.
// ---------------------------------------------------------------------------
__global__ void k_packK() {
    extern __shared__ float ksm[];               // 16384 floats
    int kb = blockIdx.x, b = blockIdx.y;
    int m0 = kb * 64;

    for (int i = threadIdx.x; i < 8192; i += 256) {
        int m = i & 63, c = i >> 6;
        float v = g_theta[((size_t)(b * CH + c)) * N_ + m0 + m];
        float hf = __uint_as_float(f2tf32(v));
        float lo = __uint_as_float(f2tf32(v - hf));
        int ks = c >> 3, hb = (c >> 2) & 1, l = c & 3;
        int nt = m >> 3, g = m & 7;
        int lane = (g << 2) | l;
        int idx  = ((ks * 8 + nt) * 32 + lane) * 4;
        ksm[idx + hb]     = hf;
        ksm[idx + 2 + hb] = lo;
    }
    __syncthreads();

    float4* dst = (float4*)(g_Kpk + ((size_t)(b * 64 + kb)) * 16384);
    const float4* src = (const float4*)ksm;
    for (int i = threadIdx.x; i < 4096; i += 256) dst[i] = src[i];
}

// ---------------------------------------------------------------------------
// K2: flash attention v3. S via 3xTF32 mma.sync, PV via fp32 FFMA.
// BM=128, BN=64, 512 threads, grid (32, BATCH).
// S mapping: warp (wm=wid>>2, wn=wid&3) owns a 32x16 S tile (2x2 m16n8k8).
// PV mapping: warp wid owns rows wid*8..+7, lane spans 128 channels (4 each).
// Row state (m, l, alpha) lives in smem; two cross-warp reductions per tile.
// ---------------------------------------------------------------------------
__global__ void __launch_bounds__(512, 1)
k_attn(float* __restrict__ out) {
    extern __shared__ float sm[];
    float*  Qh   = sm;                       // 16384
    __half* Qlh  = (__half*)(sm + 16384);    // 16384 halves
    float*  Kf   = sm + 24576;               // 16384 (K frags; aliased by Ps)
    float*  Ps   = Kf;                       // 128 x 68
    float*  VsT  = sm + 40960;               // 64 x 132 = 8448
    float*  pmax = sm + 49408;               // 128 x 4
    float*  psum = sm + 49920;               // 128 x 4
    float*  s_mi = sm + 50432;               // 128
    float*  s_li = sm + 50560;               // 128
    float*  s_al = sm + 50688;               // 128   (total 50816 floats)

    int b    = blockIdx.y;
    int n0   = blockIdx.x << 7;
    int tid  = threadIdx.x;
    int lane = tid & 31, wid = tid >> 5;
    int wm = wid >> 2, wn = wid & 3;
    int g  = lane >> 2, l  = lane & 3;
    int r0v = wid << 3;                      // PV rows
    int cx  = lane << 2;                     // PV channels

    // persistent Q fragments
    {
        const float4* qsrc = (const float4*)(g_Qh + ((size_t)(b * 32 + blockIdx.x)) * 16384);
        float4* qdst = (float4*)Qh;
        for (int i = tid; i < 4096; i += 512) qdst[i] = qsrc[i];
        const uint4* lsrc = (const uint4*)(g_Qlo + ((size_t)(b * 32 + blockIdx.x)) * 8192);
        uint4* ldst = (uint4*)Qlh;
        for (int i = tid; i < 2048; i += 512) ldst[i] = lsrc[i];
    }
    if (tid < 128) { s_mi[tid] = -INFINITY; s_li[tid] = 0.f; }

    float O[8][4];
#pragma unroll
    for (int i = 0; i < 8; i++)
#pragma unroll
        for (int j = 0; j < 4; j++) O[i][j] = 0.f;

    for (int m0 = 0; m0 < N_; m0 += 64) {
        __syncthreads();   // prev PV / P reads done; initial loads done

        {
            const float4* ksrc = (const float4*)(g_Kpk + ((size_t)(b * 64 + (m0 >> 6))) * 16384);
            float4* kdst = (float4*)Kf;
            for (int i = tid; i < 4096; i += 512) kdst[i] = ksrc[i];
            const float4* vsrc = (const float4*)(g_rsT + ((size_t)(b * N_ + m0)) * CH);
            for (int i = tid; i < 2048; i += 512) {
                int mm = i >> 5, cq = (i & 31) << 2;
                *(float4*)(VsT + mm * 132 + cq) = vsrc[i];
            }
        }
        __syncthreads();

        // ---- S-GEMM: 3xTF32 ----
        float S[2][2][4];
#pragma unroll
        for (int mt = 0; mt < 2; mt++)
#pragma unroll
            for (int nt = 0; nt < 2; nt++)
#pragma unroll
                for (int j = 0; j < 4; j++) S[mt][nt][j] = 0.f;

#pragma unroll 4
        for (int ks = 0; ks < 16; ks++) {
            unsigned int ah[2][4], al[2][4];
#pragma unroll
            for (int mt = 0; mt < 2; mt++) {
                int idx = ((ks * 8 + (wm * 2 + mt)) * 32 + lane) * 4;
                float4 a = *(const float4*)(Qh + idx);
                ah[mt][0] = __float_as_uint(a.x); ah[mt][1] = __float_as_uint(a.y);
                ah[mt][2] = __float_as_uint(a.z); ah[mt][3] = __float_as_uint(a.w);
                const __half2* ph = (const __half2*)(Qlh + idx);
                float2 f01 = __half22float2(ph[0]);
                float2 f23 = __half22float2(ph[1]);
                al[mt][0] = __float_as_uint(f01.x); al[mt][1] = __float_as_uint(f01.y);
                al[mt][2] = __float_as_uint(f23.x); al[mt][3] = __float_as_uint(f23.y);
            }
#pragma unroll
            for (int nt = 0; nt < 2; nt++) {
                float4 kf = *(const float4*)(Kf + ((ks * 8 + (wn * 2 + nt)) * 32 + lane) * 4);
                unsigned int bh0 = __float_as_uint(kf.x), bh1 = __float_as_uint(kf.y);
                unsigned int bl0 = __float_as_uint(kf.z), bl1 = __float_as_uint(kf.w);
#pragma unroll
                for (int mt = 0; mt < 2; mt++) {
                    mma_tf32(S[mt][nt], ah[mt][0], ah[mt][1], ah[mt][2], ah[mt][3], bh0, bh1);
                    mma_tf32(S[mt][nt], al[mt][0], al[mt][1], al[mt][2], al[mt][3], bh0, bh1);
                    mma_tf32(S[mt][nt], ah[mt][0], ah[mt][1], ah[mt][2], ah[mt][3], bl0, bl1);
                }
            }
        }

        // ---- row-max partials (per C-fragment row) ----
#pragma unroll
        for (int mt = 0; mt < 2; mt++)
#pragma unroll
            for (int hb = 0; hb < 2; hb++) {
                float v = fmaxf(fmaxf(S[mt][0][2 * hb], S[mt][0][2 * hb + 1]),
                                fmaxf(S[mt][1][2 * hb], S[mt][1][2 * hb + 1]));
                v = fmaxf(v, __shfl_xor_sync(0xffffffffu, v, 1));
                v = fmaxf(v, __shfl_xor_sync(0xffffffffu, v, 2));
                if (l == 0) pmax[(wm * 32 + mt * 16 + hb * 8 + g) * 4 + wn] = v;
            }
        __syncthreads();   // (A) also: Kf fully consumed

        if (tid < 128) {
            float4 pm = *(const float4*)(pmax + tid * 4);
            float vmax = fmaxf(fmaxf(pm.x, pm.y), fmaxf(pm.z, pm.w));
            float mo = s_mi[tid];
            float mn = fmaxf(mo, vmax);
            s_al[tid] = exp2f((mo - mn) * SCALE2);
            s_mi[tid] = mn;
        }
        __syncthreads();   // (B)

        // rescale O (PV mapping)
#pragma unroll
        for (int i = 0; i < 8; i++) {
            float a = s_al[r0v + i];
#pragma unroll
            for (int j = 0; j < 4; j++) O[i][j] *= a;
        }

        // ---- P = exp2((S-m)*SCALE2), write frags, row-sum partials ----
#pragma unroll
        for (int mt = 0; mt < 2; mt++)
#pragma unroll
            for (int hb = 0; hb < 2; hb++) {
                int row = wm * 32 + mt * 16 + hb * 8 + g;
                float mn = s_mi[row];
                float p00 = exp2f((S[mt][0][2 * hb]     - mn) * SCALE2);
                float p01 = exp2f((S[mt][0][2 * hb + 1] - mn) * SCALE2);
                float p10 = exp2f((S[mt][1][2 * hb]     - mn) * SCALE2);
                float p11 = exp2f((S[mt][1][2 * hb + 1] - mn) * SCALE2);
                *(float2*)(Ps + row * 68 + wn * 16 + 2 * l)     = make_float2(p00, p01);
                *(float2*)(Ps + row * 68 + wn * 16 + 8 + 2 * l) = make_float2(p10, p11);
                float s = (p00 + p01) + (p10 + p11);
                s += __shfl_xor_sync(0xffffffffu, s, 1);
                s += __shfl_xor_sync(0xffffffffu, s, 2);
                if (l == 0) psum[row * 4 + wn] = s;
            }
        __syncthreads();   // (C) P + psum visible

        if (tid < 128) {
            float4 ps4 = *(const float4*)(psum + tid * 4);
            s_li[tid] = s_li[tid] * s_al[tid] + ((ps4.x + ps4.y) + (ps4.z + ps4.w));
        }

        // ---- O += P @ V^T (fp32 FFMA, broadcast P) ----
#pragma unroll 2
        for (int mm0 = 0; mm0 < 64; mm0 += 4) {
            float4 v0 = *(const float4*)(VsT + (mm0 + 0) * 132 + cx);
            float4 v1 = *(const float4*)(VsT + (mm0 + 1) * 132 + cx);
            float4 v2 = *(const float4*)(VsT + (mm0 + 2) * 132 + cx);
            float4 v3 = *(const float4*)(VsT + (mm0 + 3) * 132 + cx);
#pragma unroll
            for (int i = 0; i < 8; i++) {
                float4 p = *(const float4*)(Ps + (r0v + i) * 68 + mm0); // broadcast
                O[i][0] += p.x * v0.x; O[i][1] += p.x * v0.y; O[i][2] += p.x * v0.z; O[i][3] += p.x * v0.w;
                O[i][0] += p.y * v1.x; O[i][1] += p.y * v1.y; O[i][2] += p.y * v1.z; O[i][3] += p.y * v1.w;
                O[i][0] += p.z * v2.x; O[i][1] += p.z * v2.y; O[i][2] += p.z * v2.z; O[i][3] += p.z * v2.w;
                O[i][0] += p.w * v3.x; O[i][1] += p.w * v3.y; O[i][2] += p.w * v3.z; O[i][3] += p.w * v3.w;
            }
        }
    }

    __syncthreads();   // s_li/s_mi final values visible

    float* yout = out;
    float* loc  = out + (size_t)BATCH * CH * N_;
#pragma unroll
    for (int i = 0; i < 8; i++) {
        int   rl  = r0v + i;
        int   r   = n0 + rl;
        float inv = 1.0f / s_li[rl];
        float sc  = s_mi[rl] * inv;
#pragma unroll
        for (int j = 0; j < 4; j++)
            yout[((size_t)(b * CH + cx + j)) * N_ + r] = O[i][j] * sc;
    }
    if (tid < 128) loc[(size_t)b * N_ + n0 + tid] = 1.0f / s_li[tid];
}

// ---------------------------------------------------------------------------
extern "C" void kernel_launch(void* const* d_in, const int* in_sizes, int n_in,
                              void* d_out, int out_size) {
    const float* m_in = (const float*)d_in[0];
    const float* rs   = (const float*)d_in[1];
    const float* thw  = (const float*)d_in[2];
    const float* phw  = (const float*)d_in[4];
    float* out = (float*)d_out;

    k_means<<<1024, 256>>>(m_in, rs);
    k_proj<<<dim3(N_ / 16, BATCH, 2), 128>>>(m_in, rs, thw, phw);
    k_transpose<<<dim3(N_ / 32, CH / 32, BATCH), dim3(32, 8)>>>(rs);

    cudaFuncSetAttribute(k_packQ, cudaFuncAttributeMaxDynamicSharedMemorySize, 98304);
    k_packQ<<<dim3(32, BATCH), 256, 98304>>>();
    cudaFuncSetAttribute(k_packK, cudaFuncAttributeMaxDynamicSharedMemorySize, 65536);
    k_packK<<<dim3(64, BATCH), 256, 65536>>>();

    size_t smem = (size_t)50816 * sizeof(float);
    cudaFuncSetAttribute(k_attn, cudaFuncAttributeMaxDynamicSharedMemorySize, (int)smem);
    k_attn<<<dim3(N_ / 128, BATCH), 512, smem>>>(out);
}

// round 6
// speedup vs baseline: 1.5647x; 1.5647x over previous
#include <cuda_runtime.h>
#include <cuda_fp16.h>
#include <math.h>

#define BATCH 4
#define CH    128
#define N_    4096
#define EPSV  2.220446049250313e-16f
#define SCALE2 144.26950408889634f   // 100 * log2(e)

// ---------------------------------------------------------------------------
// Device scratch
// ---------------------------------------------------------------------------
__device__ float g_xbar[2 * BATCH * CH];
__device__ float g_theta[BATCH * CH * N_];        // keys    [b][c][m]
__device__ float g_phi[BATCH * CH * N_];          // queries [b][c][n]
__device__ float g_Qh [BATCH * 32 * 16384];       // Q hi, A-frag order per 128-row block
__device__ unsigned int g_Qlo[BATCH * 32 * 8192]; // Q lo (f16 pairs), same order
__device__ float g_Kpk[BATCH * 64 * 16384];       // K packed (b0h,b1h,b0l,b1l) per 64-key blk
__device__ uint4 g_Vpk[BATCH * 64 * 2048];        // V B-frags (vh01,vh89,vl01,vl89) per blk

__device__ __forceinline__ unsigned int f2tf32(float x) {
    unsigned int r;
    asm("cvt.rna.tf32.f32 %0, %1;" : "=r"(r) : "f"(x));
    return r;
}

__device__ __forceinline__ void mma_tf32(float c[4],
                                         unsigned int a0, unsigned int a1,
                                         unsigned int a2, unsigned int a3,
                                         unsigned int b0, unsigned int b1) {
    asm volatile("mma.sync.aligned.m16n8k8.row.col.f32.tf32.tf32.f32 "
                 "{%0,%1,%2,%3}, {%4,%5,%6,%7}, {%8,%9}, {%0,%1,%2,%3};\n"
                 : "+f"(c[0]), "+f"(c[1]), "+f"(c[2]), "+f"(c[3])
                 : "r"(a0), "r"(a1), "r"(a2), "r"(a3), "r"(b0), "r"(b1));
}

__device__ __forceinline__ void mma_f16(float c[4],
                                        unsigned int a0, unsigned int a1,
                                        unsigned int a2, unsigned int a3,
                                        unsigned int b0, unsigned int b1) {
    asm volatile("mma.sync.aligned.m16n8k16.row.col.f32.f16.f16.f32 "
                 "{%0,%1,%2,%3}, {%4,%5,%6,%7}, {%8,%9}, {%0,%1,%2,%3};\n"
                 : "+f"(c[0]), "+f"(c[1]), "+f"(c[2]), "+f"(c[3])
                 : "r"(a0), "r"(a1), "r"(a2), "r"(a3), "r"(b0), "r"(b1));
}

__device__ __forceinline__ unsigned int h2u(__half2 h) {
    return *reinterpret_cast<unsigned int*>(&h);
}

// ---------------------------------------------------------------------------
// K0: spatial means
// ---------------------------------------------------------------------------
__global__ void k_means(const float* __restrict__ m_in, const float* __restrict__ rs) {
    int row   = blockIdx.x;
    int which = row >> 9;
    int bc    = row & 511;
    const float* src = which ? m_in : rs;
    const float* p = src + (size_t)bc * N_;

    float s = 0.f;
    for (int i = threadIdx.x; i < N_; i += 256) s += p[i];

    __shared__ float sh[256];
    sh[threadIdx.x] = s;
    __syncthreads();
    for (int off = 128; off > 0; off >>= 1) {
        if (threadIdx.x < off) sh[threadIdx.x] += sh[threadIdx.x + off];
        __syncthreads();
    }
    if (threadIdx.x == 0) g_xbar[which * 512 + bc] = sh[0] * (1.0f / N_);
}

// ---------------------------------------------------------------------------
// K1: projection + mean-center + L2-normalize (bias cancels under centering)
// ---------------------------------------------------------------------------
__global__ void k_proj(const float* __restrict__ m_in, const float* __restrict__ rs,
                       const float* __restrict__ theta_w, const float* __restrict__ phi_w) {
    int tile  = blockIdx.x;
    int b     = blockIdx.y;
    int which = blockIdx.z;
    const float* X = which ? m_in : rs;
    const float* W = which ? phi_w : theta_w;
    float* OUT     = which ? g_phi : g_theta;
    const float* xbar = &g_xbar[which * 512 + b * CH];

    int o  = threadIdx.x;
    int n0 = tile * 16;

    __shared__ float Ws[128 * 33];
    __shared__ float xs[32 * 16];
    __shared__ float sq[128 * 17];

    float acc[16];
#pragma unroll
    for (int j = 0; j < 16; j++) acc[j] = 0.f;

    for (int c0 = 0; c0 < CH; c0 += 32) {
        for (int i = threadIdx.x; i < 128 * 32; i += 128) {
            int oo = i >> 5, cc = i & 31;
            Ws[oo * 33 + cc] = W[oo * CH + c0 + cc];
        }
        for (int i = threadIdx.x; i < 32 * 16; i += 128) {
            int cc = i >> 4;
            int j  = i & 15;
            int c  = c0 + cc;
            xs[i] = X[((size_t)(b * CH + c)) * N_ + n0 + j] - xbar[c];
        }
        __syncthreads();
#pragma unroll 8
        for (int cc = 0; cc < 32; cc++) {
            float w = Ws[o * 33 + cc];
#pragma unroll
            for (int j = 0; j < 16; j++) acc[j] += w * xs[cc * 16 + j];
        }
        __syncthreads();
    }

#pragma unroll
    for (int j = 0; j < 16; j++) sq[o * 17 + j] = acc[j] * acc[j];
    for (int off = 64; off > 0; off >>= 1) {
        __syncthreads();
        if (o < off) {
#pragma unroll
            for (int j = 0; j < 16; j++) sq[o * 17 + j] += sq[(o + off) * 17 + j];
        }
    }
    __syncthreads();

#pragma unroll
    for (int j = 0; j < 16; j++) {
        float norm = sqrtf(sq[j]) + EPSV;
        OUT[((size_t)(b * CH + o)) * N_ + n0 + j] = acc[j] / norm;
    }
}

// ---------------------------------------------------------------------------
// Pack Q (phi): m16n8k8 A-frag order, hi tf32-in-f32 + lo f16.
// ---------------------------------------------------------------------------
__global__ void k_packQ() {
    extern __shared__ char psm[];
    float*  hi_s = (float*)psm;                  // 16384 floats
    __half* lo_s = (__half*)(psm + 65536);       // 16384 halves
    int blk = blockIdx.x, b = blockIdx.y;
    int n0 = blk * 128;

    for (int i = threadIdx.x; i < 16384; i += 256) {
        int r = i & 127, c = i >> 7;
        float v = g_phi[((size_t)(b * CH + c)) * N_ + n0 + r];
        float hf = __uint_as_float(f2tf32(v));
        float lo = v - hf;
        int rr = r & 15, mt = r >> 4, g = rr & 7, hb = rr >> 3;
        int cc = c & 7,  ks = c >> 3, l = cc & 3, ch = cc >> 2;
        int lane = (g << 2) | l;
        int j    = (ch << 1) | hb;
        int idx  = ((ks * 8 + mt) * 32 + lane) * 4 + j;
        hi_s[idx] = hf;
        lo_s[idx] = __float2half(lo);
    }
    __syncthreads();

    float4* hod = (float4*)(g_Qh + ((size_t)(b * 32 + blk)) * 16384);
    const float4* his = (const float4*)hi_s;
    for (int i = threadIdx.x; i < 4096; i += 256) hod[i] = his[i];

    uint4* lod = (uint4*)(g_Qlo + ((size_t)(b * 32 + blk)) * 8192);
    const uint4* los = (const uint4*)lo_s;
    for (int i = threadIdx.x; i < 2048; i += 256) lod[i] = los[i];
}

// ---------------------------------------------------------------------------
// Pack K (theta): B-frag order, float4 = (b0h, b1h, b0l, b1l).
// ---------------------------------------------------------------------------
__global__ void k_packK() {
    extern __shared__ float ksm[];               // 16384 floats
    int kb = blockIdx.x, b = blockIdx.y;
    int m0 = kb * 64;

    for (int i = threadIdx.x; i < 8192; i += 256) {
        int m = i & 63, c = i >> 6;
        float v = g_theta[((size_t)(b * CH + c)) * N_ + m0 + m];
        float hf = __uint_as_float(f2tf32(v));
        float lo = __uint_as_float(f2tf32(v - hf));
        int ks = c >> 3, hb = (c >> 2) & 1, l = c & 3;
        int nt = m >> 3, g = m & 7;
        int lane = (g << 2) | l;
        int idx  = ((ks * 8 + nt) * 32 + lane) * 4;
        ksm[idx + hb]     = hf;
        ksm[idx + 2 + hb] = lo;
    }
    __syncthreads();

    float4* dst = (float4*)(g_Kpk + ((size_t)(b * 64 + kb)) * 16384);
    const float4* src = (const float4*)ksm;
    for (int i = threadIdx.x; i < 4096; i += 256) dst[i] = src[i];
}

// ---------------------------------------------------------------------------
// Pack V (rs) into m16n8k16 B-frag order, f16 hi + f16 lo.
// uint4 = (vh[2l,2l+1], vh[2l+8,2l+9], vl[2l,2l+1], vl[2l+8,2l+9]) at col g.
// out index o = (kt*16 + ct)*32 + lane per 64-key block.
// Staging stride 68 floats (multiple of 4 -> float4-aligned for every row).
// ---------------------------------------------------------------------------
__global__ void k_packV(const float* __restrict__ rs) {
    __shared__ float Vt[128 * 68];
    int kb = blockIdx.x, b = blockIdx.y;
    int m0 = kb * 64;

    // stage rs[b][c][m0..m0+63]
    for (int i = threadIdx.x; i < 2048; i += 256) {
        int c = i >> 4, mq = (i & 15) << 2;
        float4 v = *(const float4*)(rs + ((size_t)(b * CH + c)) * N_ + m0 + mq);
        *(float4*)(Vt + c * 68 + mq) = v;
    }
    __syncthreads();

    uint4* dst = g_Vpk + ((size_t)(b * 64 + kb)) * 2048;
    for (int o = threadIdx.x; o < 2048; o += 256) {
        int lane = o & 31, ct = (o >> 5) & 15, kt = o >> 9;
        int g = lane >> 2, l = lane & 3;
        int c = 8 * ct + g;
        int m = 16 * kt + 2 * l;
        float v0 = Vt[c * 68 + m],     v1 = Vt[c * 68 + m + 1];
        float v8 = Vt[c * 68 + m + 8], v9 = Vt[c * 68 + m + 9];
        __half h0 = __float2half_rn(v0), h1 = __float2half_rn(v1);
        __half h8 = __float2half_rn(v8), h9 = __float2half_rn(v9);
        __half l0 = __float2half_rn(v0 - __half2float(h0));
        __half l1 = __float2half_rn(v1 - __half2float(h1));
        __half l8 = __float2half_rn(v8 - __half2float(h8));
        __half l9 = __float2half_rn(v9 - __half2float(h9));
        uint4 outv;
        outv.x = h2u(__halves2half2(h0, h1));
        outv.y = h2u(__halves2half2(h8, h9));
        outv.z = h2u(__halves2half2(l0, l1));
        outv.w = h2u(__halves2half2(l8, l9));
        dst[o] = outv;
    }
}

// ---------------------------------------------------------------------------
// K2: flash attention v4 (FA2-style, register-resident P).
// 256 threads = 8 warps; warp w owns rows 16w..16w+15 (one m16 tile).
// BN=64 keys/iter. S: 3xTF32 m16n8k8. PV: 3x f16 m16n8k16.
// Softmax fully warp-local (rows live in (g,hb); reduce over l lanes).
// ---------------------------------------------------------------------------
__global__ void __launch_bounds__(256, 1)
k_attn(float* __restrict__ out) {
    extern __shared__ float sm[];
    float*  Qh  = sm;                        // 16384 floats
    __half* Qlh = (__half*)(sm + 16384);     // 16384 halves (8192 floats)
    float*  Kf  = sm + 24576;                // 16384 floats
    uint4*  Vf  = (uint4*)(sm + 40960);      // 2048 uint4 (8192 floats)
    // total 49152 floats = 192 KB

    int b    = blockIdx.y;
    int n0   = blockIdx.x << 7;
    int tid  = threadIdx.x;
    int lane = tid & 31, w = tid >> 5;
    int g = lane >> 2, l = lane & 3;

    // load persistent Q fragments
    {
        const float4* qsrc = (const float4*)(g_Qh + ((size_t)(b * 32 + blockIdx.x)) * 16384);
        float4* qdst = (float4*)Qh;
        for (int i = tid; i < 4096; i += 256) qdst[i] = qsrc[i];
        const uint4* lsrc = (const uint4*)(g_Qlo + ((size_t)(b * 32 + blockIdx.x)) * 8192);
        uint4* ldst = (uint4*)Qlh;
        for (int i = tid; i < 2048; i += 256) ldst[i] = lsrc[i];
    }

    float O[16][4];
#pragma unroll
    for (int ct = 0; ct < 16; ct++)
#pragma unroll
        for (int j = 0; j < 4; j++) O[ct][j] = 0.f;
    float mi[2] = {-INFINITY, -INFINITY};
    float li[2] = {0.f, 0.f};

    for (int kb = 0; kb < 64; kb++) {
        __syncthreads();   // previous iter's Kf/Vf reads done

        {
            const float4* ksrc = (const float4*)(g_Kpk + ((size_t)(b * 64 + kb)) * 16384);
            float4* kdst = (float4*)Kf;
#pragma unroll 4
            for (int i = tid; i < 4096; i += 256) kdst[i] = ksrc[i];
            const uint4* vsrc = g_Vpk + ((size_t)(b * 64 + kb)) * 2048;
#pragma unroll 4
            for (int i = tid; i < 2048; i += 256) Vf[i] = vsrc[i];
        }
        __syncthreads();

        // ---- S = Q^T K : 3xTF32, S[nt][4] over 8 n-tiles ----
        float S[8][4];
#pragma unroll
        for (int nt = 0; nt < 8; nt++)
#pragma unroll
            for (int j = 0; j < 4; j++) S[nt][j] = 0.f;

#pragma unroll 4
        for (int ks = 0; ks < 16; ks++) {
            int aidx = ((ks * 8 + w) * 32 + lane) * 4;
            float4 a = *(const float4*)(Qh + aidx);
            unsigned int ah0 = __float_as_uint(a.x), ah1 = __float_as_uint(a.y);
            unsigned int ah2 = __float_as_uint(a.z), ah3 = __float_as_uint(a.w);
            uint2 ul = *(const uint2*)(Qlh + aidx);
            float2 f01 = __half22float2(*reinterpret_cast<__half2*>(&ul.x));
            float2 f23 = __half22float2(*reinterpret_cast<__half2*>(&ul.y));
            unsigned int al0 = __float_as_uint(f01.x), al1 = __float_as_uint(f01.y);
            unsigned int al2 = __float_as_uint(f23.x), al3 = __float_as_uint(f23.y);
#pragma unroll
            for (int nt = 0; nt < 8; nt++) {
                float4 kf = *(const float4*)(Kf + ((ks * 8 + nt) * 32 + lane) * 4);
                unsigned int bh0 = __float_as_uint(kf.x), bh1 = __float_as_uint(kf.y);
                unsigned int bl0 = __float_as_uint(kf.z), bl1 = __float_as_uint(kf.w);
                mma_tf32(S[nt], ah0, ah1, ah2, ah3, bh0, bh1);
                mma_tf32(S[nt], al0, al1, al2, al3, bh0, bh1);
                mma_tf32(S[nt], ah0, ah1, ah2, ah3, bl0, bl1);
            }
        }

        // ---- warp-local online softmax; P overwrites S ----
#pragma unroll
        for (int hb = 0; hb < 2; hb++) {
            float vmax = -INFINITY;
#pragma unroll
            for (int nt = 0; nt < 8; nt++)
                vmax = fmaxf(vmax, fmaxf(S[nt][2 * hb], S[nt][2 * hb + 1]));
            vmax = fmaxf(vmax, __shfl_xor_sync(0xffffffffu, vmax, 1));
            vmax = fmaxf(vmax, __shfl_xor_sync(0xffffffffu, vmax, 2));
            float mnew  = fmaxf(mi[hb], vmax);
            float alpha = exp2f((mi[hb] - mnew) * SCALE2);
            mi[hb] = mnew;

            float rs_ = 0.f;
#pragma unroll
            for (int nt = 0; nt < 8; nt++) {
                float p0 = exp2f((S[nt][2 * hb]     - mnew) * SCALE2);
                float p1 = exp2f((S[nt][2 * hb + 1] - mnew) * SCALE2);
                S[nt][2 * hb]     = p0;
                S[nt][2 * hb + 1] = p1;
                rs_ += p0 + p1;
            }
            rs_ += __shfl_xor_sync(0xffffffffu, rs_, 1);
            rs_ += __shfl_xor_sync(0xffffffffu, rs_, 2);
            li[hb] = li[hb] * alpha + rs_;

#pragma unroll
            for (int ct = 0; ct < 16; ct++) {
                O[ct][2 * hb]     *= alpha;
                O[ct][2 * hb + 1] *= alpha;
            }
        }

        // ---- convert P -> f16 A-fragments (hi + lo), register-only ----
        unsigned int Pha[4][4], Pla[4][4];
#pragma unroll
        for (int kt = 0; kt < 4; kt++) {
#pragma unroll
            for (int hf2 = 0; hf2 < 2; hf2++) {
                int nt = 2 * kt + hf2;
#pragma unroll
                for (int hb = 0; hb < 2; hb++) {
                    float p0 = S[nt][2 * hb], p1 = S[nt][2 * hb + 1];
                    __half h0 = __float2half_rn(p0), h1 = __float2half_rn(p1);
                    __half e0 = __float2half_rn(p0 - __half2float(h0));
                    __half e1 = __float2half_rn(p1 - __half2float(h1));
                    Pha[kt][hf2 * 2 + hb] = h2u(__halves2half2(h0, h1));
                    Pla[kt][hf2 * 2 + hb] = h2u(__halves2half2(e0, e1));
                }
            }
        }

        // ---- O += P @ V : 3x f16 m16n8k16 ----
#pragma unroll
        for (int kt = 0; kt < 4; kt++) {
#pragma unroll
            for (int ct = 0; ct < 16; ct++) {
                uint4 vf = Vf[(kt * 16 + ct) * 32 + lane];
                mma_f16(O[ct], Pha[kt][0], Pha[kt][1], Pha[kt][2], Pha[kt][3], vf.x, vf.y);
                mma_f16(O[ct], Pla[kt][0], Pla[kt][1], Pla[kt][2], Pla[kt][3], vf.x, vf.y);
                mma_f16(O[ct], Pha[kt][0], Pha[kt][1], Pha[kt][2], Pha[kt][3], vf.z, vf.w);
            }
        }
    }

    // ---- epilogue ----
    float* yout = out;
    float* loc  = out + (size_t)BATCH * CH * N_;
#pragma unroll
    for (int hb = 0; hb < 2; hb++) {
        float inv = 1.0f / li[hb];
        float sc  = mi[hb] * inv;
        int   r   = n0 + 16 * w + g + 8 * hb;
#pragma unroll
        for (int ct = 0; ct < 16; ct++) {
            int c0 = 8 * ct + 2 * l;
            yout[((size_t)(b * CH + c0)) * N_ + r]     = O[ct][2 * hb]     * sc;
            yout[((size_t)(b * CH + c0 + 1)) * N_ + r] = O[ct][2 * hb + 1] * sc;
        }
        if (l == 0) loc[(size_t)b * N_ + r] = inv;
    }
}

// ---------------------------------------------------------------------------
extern "C" void kernel_launch(void* const* d_in, const int* in_sizes, int n_in,
                              void* d_out, int out_size) {
    const float* m_in = (const float*)d_in[0];
    const float* rs   = (const float*)d_in[1];
    const float* thw  = (const float*)d_in[2];
    const float* phw  = (const float*)d_in[4];
    float* out = (float*)d_out;

    k_means<<<1024, 256>>>(m_in, rs);
    k_proj<<<dim3(N_ / 16, BATCH, 2), 128>>>(m_in, rs, thw, phw);

    cudaFuncSetAttribute(k_packQ, cudaFuncAttributeMaxDynamicSharedMemorySize, 98304);
    k_packQ<<<dim3(32, BATCH), 256, 98304>>>();
    cudaFuncSetAttribute(k_packK, cudaFuncAttributeMaxDynamicSharedMemorySize, 65536);
    k_packK<<<dim3(64, BATCH), 256, 65536>>>();
    k_packV<<<dim3(64, BATCH), 256>>>(rs);

    size_t smem = (size_t)49152 * sizeof(float);
    cudaFuncSetAttribute(k_attn, cudaFuncAttributeMaxDynamicSharedMemorySize, (int)smem);
    k_attn<<<dim3(N_ / 128, BATCH), 256, smem>>>(out);
}

// round 7
// speedup vs baseline: 1.7423x; 1.1135x over previous
#include <cuda_runtime.h>
#include <cuda_fp16.h>
#include <math.h>

#define BATCH 4
#define CH    128
#define N_    4096
#define EPSV  2.220446049250313e-16f
#define SCALE2 144.26950408889634f   // 100 * log2(e)

// ---------------------------------------------------------------------------
// Device scratch
// ---------------------------------------------------------------------------
__device__ float g_xbar[2 * BATCH * CH];
__device__ float g_theta[BATCH * CH * N_];        // keys    [b][c][m]
__device__ float g_phi[BATCH * CH * N_];          // queries [b][c][n]
__device__ float g_Qh [BATCH * 32 * 16384];       // Q hi, A-frag order per 128-row block
__device__ unsigned int g_Qlo[BATCH * 32 * 8192]; // Q lo (f16 pairs), same order
__device__ float g_Kpk[BATCH * 64 * 12288];       // K: hi f32x2 [0,8192) + lo f16x2 [8192,12288)
__device__ uint4 g_Vpk[BATCH * 64 * 2048];        // V B-frags (vh01,vh89,vl01,vl89) per blk

__device__ __forceinline__ unsigned int f2tf32(float x) {
    unsigned int r;
    asm("cvt.rna.tf32.f32 %0, %1;" : "=r"(r) : "f"(x));
    return r;
}

__device__ __forceinline__ void mma_tf32(float c[4],
                                         unsigned int a0, unsigned int a1,
                                         unsigned int a2, unsigned int a3,
                                         unsigned int b0, unsigned int b1) {
    asm volatile("mma.sync.aligned.m16n8k8.row.col.f32.tf32.tf32.f32 "
                 "{%0,%1,%2,%3}, {%4,%5,%6,%7}, {%8,%9}, {%0,%1,%2,%3};\n"
                 : "+f"(c[0]), "+f"(c[1]), "+f"(c[2]), "+f"(c[3])
                 : "r"(a0), "r"(a1), "r"(a2), "r"(a3), "r"(b0), "r"(b1));
}

__device__ __forceinline__ void mma_f16(float c[4],
                                        unsigned int a0, unsigned int a1,
                                        unsigned int a2, unsigned int a3,
                                        unsigned int b0, unsigned int b1) {
    asm volatile("mma.sync.aligned.m16n8k16.row.col.f32.f16.f16.f32 "
                 "{%0,%1,%2,%3}, {%4,%5,%6,%7}, {%8,%9}, {%0,%1,%2,%3};\n"
                 : "+f"(c[0]), "+f"(c[1]), "+f"(c[2]), "+f"(c[3])
                 : "r"(a0), "r"(a1), "r"(a2), "r"(a3), "r"(b0), "r"(b1));
}

__device__ __forceinline__ unsigned int h2u(__half2 h) {
    return *reinterpret_cast<unsigned int*>(&h);
}

__device__ __forceinline__ void cpasync16(void* s, const void* g) {
    unsigned int saddr = (unsigned int)__cvta_generic_to_shared(s);
    asm volatile("cp.async.cg.shared.global [%0], [%1], 16;\n" :: "r"(saddr), "l"(g));
}

// ---------------------------------------------------------------------------
// K0: spatial means
// ---------------------------------------------------------------------------
__global__ void k_means(const float* __restrict__ m_in, const float* __restrict__ rs) {
    int row   = blockIdx.x;
    int which = row >> 9;
    int bc    = row & 511;
    const float* src = which ? m_in : rs;
    const float* p = src + (size_t)bc * N_;

    float s = 0.f;
    for (int i = threadIdx.x; i < N_; i += 256) s += p[i];

    __shared__ float sh[256];
    sh[threadIdx.x] = s;
    __syncthreads();
    for (int off = 128; off > 0; off >>= 1) {
        if (threadIdx.x < off) sh[threadIdx.x] += sh[threadIdx.x + off];
        __syncthreads();
    }
    if (threadIdx.x == 0) g_xbar[which * 512 + bc] = sh[0] * (1.0f / N_);
}

// ---------------------------------------------------------------------------
// K1: projection + mean-center + L2-normalize (bias cancels under centering)
// ---------------------------------------------------------------------------
__global__ void k_proj(const float* __restrict__ m_in, const float* __restrict__ rs,
                       const float* __restrict__ theta_w, const float* __restrict__ phi_w) {
    int tile  = blockIdx.x;
    int b     = blockIdx.y;
    int which = blockIdx.z;
    const float* X = which ? m_in : rs;
    const float* W = which ? phi_w : theta_w;
    float* OUT     = which ? g_phi : g_theta;
    const float* xbar = &g_xbar[which * 512 + b * CH];

    int o  = threadIdx.x;
    int n0 = tile * 16;

    __shared__ float Ws[128 * 33];
    __shared__ float xs[32 * 16];
    __shared__ float sq[128 * 17];

    float acc[16];
#pragma unroll
    for (int j = 0; j < 16; j++) acc[j] = 0.f;

    for (int c0 = 0; c0 < CH; c0 += 32) {
        for (int i = threadIdx.x; i < 128 * 32; i += 128) {
            int oo = i >> 5, cc = i & 31;
            Ws[oo * 33 + cc] = W[oo * CH + c0 + cc];
        }
        for (int i = threadIdx.x; i < 32 * 16; i += 128) {
            int cc = i >> 4;
            int j  = i & 15;
            int c  = c0 + cc;
            xs[i] = X[((size_t)(b * CH + c)) * N_ + n0 + j] - xbar[c];
        }
        __syncthreads();
#pragma unroll 8
        for (int cc = 0; cc < 32; cc++) {
            float w = Ws[o * 33 + cc];
#pragma unroll
            for (int j = 0; j < 16; j++) acc[j] += w * xs[cc * 16 + j];
        }
        __syncthreads();
    }

#pragma unroll
    for (int j = 0; j < 16; j++) sq[o * 17 + j] = acc[j] * acc[j];
    for (int off = 64; off > 0; off >>= 1) {
        __syncthreads();
        if (o < off) {
#pragma unroll
            for (int j = 0; j < 16; j++) sq[o * 17 + j] += sq[(o + off) * 17 + j];
        }
    }
    __syncthreads();

#pragma unroll
    for (int j = 0; j < 16; j++) {
        float norm = sqrtf(sq[j]) + EPSV;
        OUT[((size_t)(b * CH + o)) * N_ + n0 + j] = acc[j] / norm;
    }
}

// ---------------------------------------------------------------------------
// Pack Q (phi): m16n8k8 A-frag order, hi tf32-in-f32 + lo f16.
// ---------------------------------------------------------------------------
__global__ void k_packQ() {
    extern __shared__ char psm[];
    float*  hi_s = (float*)psm;                  // 16384 floats
    __half* lo_s = (__half*)(psm + 65536);       // 16384 halves
    int blk = blockIdx.x, b = blockIdx.y;
    int n0 = blk * 128;

    for (int i = threadIdx.x; i < 16384; i += 256) {
        int r = i & 127, c = i >> 7;
        float v = g_phi[((size_t)(b * CH + c)) * N_ + n0 + r];
        float hf = __uint_as_float(f2tf32(v));
        float lo = v - hf;
        int rr = r & 15, mt = r >> 4, g = rr & 7, hb = rr >> 3;
        int cc = c & 7,  ks = c >> 3, l = cc & 3, ch = cc >> 2;
        int lane = (g << 2) | l;
        int j    = (ch << 1) | hb;
        int idx  = ((ks * 8 + mt) * 32 + lane) * 4 + j;
        hi_s[idx] = hf;
        lo_s[idx] = __float2half(lo);
    }
    __syncthreads();

    float4* hod = (float4*)(g_Qh + ((size_t)(b * 32 + blk)) * 16384);
    const float4* his = (const float4*)hi_s;
    for (int i = threadIdx.x; i < 4096; i += 256) hod[i] = his[i];

    uint4* lod = (uint4*)(g_Qlo + ((size_t)(b * 32 + blk)) * 8192);
    const uint4* los = (const uint4*)lo_s;
    for (int i = threadIdx.x; i < 2048; i += 256) lod[i] = los[i];
}

// ---------------------------------------------------------------------------
// Pack K (theta): hi region [0,8192) float2 per frag; lo region [8192,12288)
// f16x2 per frag (b0 low half, b1 high half).
// ---------------------------------------------------------------------------
__global__ void k_packK() {
    extern __shared__ float ksm[];               // 12288 floats
    int kb = blockIdx.x, b = blockIdx.y;
    int m0 = kb * 64;

    for (int i = threadIdx.x; i < 8192; i += 256) {
        int m = i & 63, c = i >> 6;
        float v = g_theta[((size_t)(b * CH + c)) * N_ + m0 + m];
        float hf = __uint_as_float(f2tf32(v));
        float lo = v - hf;
        int ks = c >> 3, hb = (c >> 2) & 1, l = c & 3;
        int nt = m >> 3, g = m & 7;
        int lane = (g << 2) | l;
        int frag = (ks * 8 + nt) * 32 + lane;
        ksm[frag * 2 + hb] = hf;
        ((__half*)(ksm + 8192))[frag * 2 + hb] = __float2half(lo);
    }
    __syncthreads();

    float4* dst = (float4*)(g_Kpk + ((size_t)(b * 64 + kb)) * 12288);
    const float4* src = (const float4*)ksm;
    for (int i = threadIdx.x; i < 3072; i += 256) dst[i] = src[i];
}

// ---------------------------------------------------------------------------
// Pack V (rs) into m16n8k16 B-frag order, f16 hi + f16 lo.
// ---------------------------------------------------------------------------
__global__ void k_packV(const float* __restrict__ rs) {
    __shared__ float Vt[128 * 68];
    int kb = blockIdx.x, b = blockIdx.y;
    int m0 = kb * 64;

    for (int i = threadIdx.x; i < 2048; i += 256) {
        int c = i >> 4, mq = (i & 15) << 2;
        float4 v = *(const float4*)(rs + ((size_t)(b * CH + c)) * N_ + m0 + mq);
        *(float4*)(Vt + c * 68 + mq) = v;
    }
    __syncthreads();

    uint4* dst = g_Vpk + ((size_t)(b * 64 + kb)) * 2048;
    for (int o = threadIdx.x; o < 2048; o += 256) {
        int lane = o & 31, ct = (o >> 5) & 15, kt = o >> 9;
        int g = lane >> 2, l = lane & 3;
        int c = 8 * ct + g;
        int m = 16 * kt + 2 * l;
        float v0 = Vt[c * 68 + m],     v1 = Vt[c * 68 + m + 1];
        float v8 = Vt[c * 68 + m + 8], v9 = Vt[c * 68 + m + 9];
        __half h0 = __float2half_rn(v0), h1 = __float2half_rn(v1);
        __half h8 = __float2half_rn(v8), h9 = __float2half_rn(v9);
        __half l0 = __float2half_rn(v0 - __half2float(h0));
        __half l1 = __float2half_rn(v1 - __half2float(h1));
        __half l8 = __float2half_rn(v8 - __half2float(h8));
        __half l9 = __float2half_rn(v9 - __half2float(h9));
        uint4 outv;
        outv.x = h2u(__halves2half2(h0, h1));
        outv.y = h2u(__halves2half2(h8, h9));
        outv.z = h2u(__halves2half2(l0, l1));
        outv.w = h2u(__halves2half2(l8, l9));
        dst[o] = outv;
    }
}

// ---------------------------------------------------------------------------
// K2: flash attention v5. Double-buffered K/V via cp.async, f16 K-lo,
// Q-lo in registers. 256 threads = 8 warps, warp w owns rows 16w..16w+15.
// smem: Qh 64KB + 2 x (K 48KB + V 32KB) = 224KB.
// ---------------------------------------------------------------------------
#define BUF_FLOATS 20480   // 12288 K + 8192 V

__global__ void __launch_bounds__(256, 1)
k_attn(float* __restrict__ out) {
    extern __shared__ float sm[];
    float* Qh = sm;                          // 16384 floats

    int b    = blockIdx.y;
    int n0   = blockIdx.x << 7;
    int tid  = threadIdx.x;
    int lane = tid & 31, w = tid >> 5;
    int g = lane >> 2, l = lane & 3;

    // load persistent Q hi fragments into smem
    {
        const float4* qsrc = (const float4*)(g_Qh + ((size_t)(b * 32 + blockIdx.x)) * 16384);
        float4* qdst = (float4*)Qh;
        for (int i = tid; i < 4096; i += 256) qdst[i] = qsrc[i];
    }
    // Q lo fragments into registers (uint2 = 4 f16 per ks)
    uint2 qlo[16];
    {
        const uint2* qlosrc = (const uint2*)(g_Qlo + ((size_t)(b * 32 + blockIdx.x)) * 8192);
#pragma unroll
        for (int ks = 0; ks < 16; ks++)
            qlo[ks] = qlosrc[(ks * 8 + w) * 32 + lane];
    }

    // prologue: async load block 0 into buffer 0
    {
        const float4* ksrc = (const float4*)(g_Kpk + ((size_t)(b * 64 + 0)) * 12288);
        float* kd = sm + 16384;
        for (int i = tid; i < 3072; i += 256) cpasync16(kd + i * 4, ksrc + i);
        const uint4* vsrc = g_Vpk + ((size_t)(b * 64 + 0)) * 2048;
        float* vd = kd + 12288;
        for (int i = tid; i < 2048; i += 256) cpasync16(vd + i * 4, vsrc + i);
        asm volatile("cp.async.commit_group;\n" ::);
    }

    float O[16][4];
#pragma unroll
    for (int ct = 0; ct < 16; ct++)
#pragma unroll
        for (int j = 0; j < 4; j++) O[ct][j] = 0.f;
    float mi[2] = {-INFINITY, -INFINITY};
    float li[2] = {0.f, 0.f};

    for (int kb = 0; kb < 64; kb++) {
        int cur = kb & 1;
        float* Kc = sm + 16384 + cur * BUF_FLOATS;
        uint4* Vf = (uint4*)(Kc + 12288);

        // issue next block's loads into the other buffer
        if (kb < 63) {
            float* kd = sm + 16384 + (1 - cur) * BUF_FLOATS;
            const float4* ksrc = (const float4*)(g_Kpk + ((size_t)(b * 64 + kb + 1)) * 12288);
            for (int i = tid; i < 3072; i += 256) cpasync16(kd + i * 4, ksrc + i);
            const uint4* vsrc = g_Vpk + ((size_t)(b * 64 + kb + 1)) * 2048;
            float* vd = kd + 12288;
            for (int i = tid; i < 2048; i += 256) cpasync16(vd + i * 4, vsrc + i);
            asm volatile("cp.async.commit_group;\n" ::);
            asm volatile("cp.async.wait_group 1;\n" ::);
        } else {
            asm volatile("cp.async.wait_group 0;\n" ::);
        }
        __syncthreads();   // current buffer data visible to all

        // ---- S = Q^T K : 3xTF32 ----
        float S[8][4];
#pragma unroll
        for (int nt = 0; nt < 8; nt++)
#pragma unroll
            for (int j = 0; j < 4; j++) S[nt][j] = 0.f;

#pragma unroll 4
        for (int ks = 0; ks < 16; ks++) {
            float4 a = *(const float4*)(Qh + ((ks * 8 + w) * 32 + lane) * 4);
            unsigned int ah0 = __float_as_uint(a.x), ah1 = __float_as_uint(a.y);
            unsigned int ah2 = __float_as_uint(a.z), ah3 = __float_as_uint(a.w);
            float2 f01 = __half22float2(*reinterpret_cast<const __half2*>(&qlo[ks].x));
            float2 f23 = __half22float2(*reinterpret_cast<const __half2*>(&qlo[ks].y));
            unsigned int al0 = __float_as_uint(f01.x), al1 = __float_as_uint(f01.y);
            unsigned int al2 = __float_as_uint(f23.x), al3 = __float_as_uint(f23.y);
#pragma unroll
            for (int nt = 0; nt < 8; nt++) {
                int frag = (ks * 8 + nt) * 32 + lane;
                float2 kh = *(const float2*)(Kc + frag * 2);
                __half2 kl2 = *(const __half2*)(Kc + 8192 + frag);
                float2 kl = __half22float2(kl2);
                unsigned int bh0 = __float_as_uint(kh.x), bh1 = __float_as_uint(kh.y);
                unsigned int bl0 = __float_as_uint(kl.x), bl1 = __float_as_uint(kl.y);
                mma_tf32(S[nt], ah0, ah1, ah2, ah3, bh0, bh1);
                mma_tf32(S[nt], al0, al1, al2, al3, bh0, bh1);
                mma_tf32(S[nt], ah0, ah1, ah2, ah3, bl0, bl1);
            }
        }

        // ---- warp-local online softmax; P overwrites S ----
#pragma unroll
        for (int hb = 0; hb < 2; hb++) {
            float vmax = -INFINITY;
#pragma unroll
            for (int nt = 0; nt < 8; nt++)
                vmax = fmaxf(vmax, fmaxf(S[nt][2 * hb], S[nt][2 * hb + 1]));
            vmax = fmaxf(vmax, __shfl_xor_sync(0xffffffffu, vmax, 1));
            vmax = fmaxf(vmax, __shfl_xor_sync(0xffffffffu, vmax, 2));
            float mnew  = fmaxf(mi[hb], vmax);
            float alpha = exp2f((mi[hb] - mnew) * SCALE2);
            mi[hb] = mnew;

            float rs_ = 0.f;
#pragma unroll
            for (int nt = 0; nt < 8; nt++) {
                float p0 = exp2f((S[nt][2 * hb]     - mnew) * SCALE2);
                float p1 = exp2f((S[nt][2 * hb + 1] - mnew) * SCALE2);
                S[nt][2 * hb]     = p0;
                S[nt][2 * hb + 1] = p1;
                rs_ += p0 + p1;
            }
            rs_ += __shfl_xor_sync(0xffffffffu, rs_, 1);
            rs_ += __shfl_xor_sync(0xffffffffu, rs_, 2);
            li[hb] = li[hb] * alpha + rs_;

#pragma unroll
            for (int ct = 0; ct < 16; ct++) {
                O[ct][2 * hb]     *= alpha;
                O[ct][2 * hb + 1] *= alpha;
            }
        }

        // ---- PV: per-kt P->f16 conversion, then 3x f16 m16n8k16 ----
#pragma unroll
        for (int kt = 0; kt < 4; kt++) {
            unsigned int Pha[4], Pla[4];
#pragma unroll
            for (int hf2 = 0; hf2 < 2; hf2++) {
                int nt = 2 * kt + hf2;
#pragma unroll
                for (int hb = 0; hb < 2; hb++) {
                    float p0 = S[nt][2 * hb], p1 = S[nt][2 * hb + 1];
                    __half h0 = __float2half_rn(p0), h1 = __float2half_rn(p1);
                    __half e0 = __float2half_rn(p0 - __half2float(h0));
                    __half e1 = __float2half_rn(p1 - __half2float(h1));
                    Pha[hf2 * 2 + hb] = h2u(__halves2half2(h0, h1));
                    Pla[hf2 * 2 + hb] = h2u(__halves2half2(e0, e1));
                }
            }
#pragma unroll
            for (int ct = 0; ct < 16; ct++) {
                uint4 vf = Vf[(kt * 16 + ct) * 32 + lane];
                mma_f16(O[ct], Pha[0], Pha[1], Pha[2], Pha[3], vf.x, vf.y);
                mma_f16(O[ct], Pla[0], Pla[1], Pla[2], Pla[3], vf.x, vf.y);
                mma_f16(O[ct], Pha[0], Pha[1], Pha[2], Pha[3], vf.z, vf.w);
            }
        }
        __syncthreads();   // done with current buffer (next-next load may overwrite)
    }

    // ---- epilogue ----
    float* yout = out;
    float* loc  = out + (size_t)BATCH * CH * N_;
#pragma unroll
    for (int hb = 0; hb < 2; hb++) {
        float inv = 1.0f / li[hb];
        float sc  = mi[hb] * inv;
        int   r   = n0 + 16 * w + g + 8 * hb;
#pragma unroll
        for (int ct = 0; ct < 16; ct++) {
            int c0 = 8 * ct + 2 * l;
            yout[((size_t)(b * CH + c0)) * N_ + r]     = O[ct][2 * hb]     * sc;
            yout[((size_t)(b * CH + c0 + 1)) * N_ + r] = O[ct][2 * hb + 1] * sc;
        }
        if (l == 0) loc[(size_t)b * N_ + r] = inv;
    }
}

// ---------------------------------------------------------------------------
extern "C" void kernel_launch(void* const* d_in, const int* in_sizes, int n_in,
                              void* d_out, int out_size) {
    const float* m_in = (const float*)d_in[0];
    const float* rs   = (const float*)d_in[1];
    const float* thw  = (const float*)d_in[2];
    const float* phw  = (const float*)d_in[4];
    float* out = (float*)d_out;

    k_means<<<1024, 256>>>(m_in, rs);
    k_proj<<<dim3(N_ / 16, BATCH, 2), 128>>>(m_in, rs, thw, phw);

    cudaFuncSetAttribute(k_packQ, cudaFuncAttributeMaxDynamicSharedMemorySize, 98304);
    k_packQ<<<dim3(32, BATCH), 256, 98304>>>();
    cudaFuncSetAttribute(k_packK, cudaFuncAttributeMaxDynamicSharedMemorySize, 49152);
    k_packK<<<dim3(64, BATCH), 256, 49152>>>();
    k_packV<<<dim3(64, BATCH), 256>>>(rs);

    size_t smem = (size_t)(16384 + 2 * BUF_FLOATS) * sizeof(float);  // 224 KB
    cudaFuncSetAttribute(k_attn, cudaFuncAttributeMaxDynamicSharedMemorySize, (int)smem);
    k_attn<<<dim3(N_ / 128, BATCH), 256, smem>>>(out);
}

// round 9
// speedup vs baseline: 2.4352x; 1.3977x over previous
#include <cuda_runtime.h>
#include <cuda_fp16.h>
#include <math.h>

#define BATCH 4
#define CH    128
#define N_    4096
#define EPSV  2.220446049250313e-16f
#define SCALE2 144.26950408889634f   // 100 * log2(e)

// ---------------------------------------------------------------------------
// Device scratch
// ---------------------------------------------------------------------------
__device__ float g_xbar[2 * BATCH * CH];
__device__ float g_theta[BATCH * CH * N_];        // keys    [b][c][m]
__device__ float g_phi[BATCH * CH * N_];          // queries [b][c][n]
__device__ uint4 g_Qpk[BATCH * 32 * 4096];        // Q A-frags: [0,2048) hi, [2048,4096) lo per blk
__device__ uint4 g_Kpk[BATCH * 64 * 2048];        // K B-frags (b0h,b1h,b0l,b1l) per 64-key blk
__device__ uint4 g_Vpk[BATCH * 64 * 2048];        // V B-frags (vh01,vh89,vl01,vl89) per blk

__device__ __forceinline__ void mma_f16(float c[4],
                                        unsigned int a0, unsigned int a1,
                                        unsigned int a2, unsigned int a3,
                                        unsigned int b0, unsigned int b1) {
    asm volatile("mma.sync.aligned.m16n8k16.row.col.f32.f16.f16.f32 "
                 "{%0,%1,%2,%3}, {%4,%5,%6,%7}, {%8,%9}, {%0,%1,%2,%3};\n"
                 : "+f"(c[0]), "+f"(c[1]), "+f"(c[2]), "+f"(c[3])
                 : "r"(a0), "r"(a1), "r"(a2), "r"(a3), "r"(b0), "r"(b1));
}

__device__ __forceinline__ unsigned int h2u(__half2 h) {
    return *reinterpret_cast<unsigned int*>(&h);
}

__device__ __forceinline__ unsigned int pack_hi(float a, float b) {
    return h2u(__halves2half2(__float2half_rn(a), __float2half_rn(b)));
}
// lo residual of f16 split
__device__ __forceinline__ unsigned int pack_lo(float a, float b) {
    __half ha = __float2half_rn(a), hb = __float2half_rn(b);
    return h2u(__halves2half2(__float2half_rn(a - __half2float(ha)),
                              __float2half_rn(b - __half2float(hb))));
}

__device__ __forceinline__ void cpasync16(void* s, const void* g) {
    unsigned int saddr = (unsigned int)__cvta_generic_to_shared(s);
    asm volatile("cp.async.cg.shared.global [%0], [%1], 16;\n" :: "r"(saddr), "l"(g));
}

// ---------------------------------------------------------------------------
// K0: spatial means
// ---------------------------------------------------------------------------
__global__ void k_means(const float* __restrict__ m_in, const float* __restrict__ rs) {
    int row   = blockIdx.x;
    int which = row >> 9;
    int bc    = row & 511;
    const float* src = which ? m_in : rs;
    const float* p = src + (size_t)bc * N_;

    float s = 0.f;
    for (int i = threadIdx.x; i < N_; i += 256) s += p[i];

    __shared__ float sh[256];
    sh[threadIdx.x] = s;
    __syncthreads();
    for (int off = 128; off > 0; off >>= 1) {
        if (threadIdx.x < off) sh[threadIdx.x] += sh[threadIdx.x + off];
        __syncthreads();
    }
    if (threadIdx.x == 0) g_xbar[which * 512 + bc] = sh[0] * (1.0f / N_);
}

// ---------------------------------------------------------------------------
// K1: projection + mean-center + L2-normalize (bias cancels under centering)
// ---------------------------------------------------------------------------
__global__ void k_proj(const float* __restrict__ m_in, const float* __restrict__ rs,
                       const float* __restrict__ theta_w, const float* __restrict__ phi_w) {
    int tile  = blockIdx.x;
    int b     = blockIdx.y;
    int which = blockIdx.z;
    const float* X = which ? m_in : rs;
    const float* W = which ? phi_w : theta_w;
    float* OUT     = which ? g_phi : g_theta;
    const float* xbar = &g_xbar[which * 512 + b * CH];

    int o  = threadIdx.x;
    int n0 = tile * 16;

    __shared__ float Ws[128 * 33];
    __shared__ float xs[32 * 16];
    __shared__ float sq[128 * 17];

    float acc[16];
#pragma unroll
    for (int j = 0; j < 16; j++) acc[j] = 0.f;

    for (int c0 = 0; c0 < CH; c0 += 32) {
        for (int i = threadIdx.x; i < 128 * 32; i += 128) {
            int oo = i >> 5, cc = i & 31;
            Ws[oo * 33 + cc] = W[oo * CH + c0 + cc];
        }
        for (int i = threadIdx.x; i < 32 * 16; i += 128) {
            int cc = i >> 4;
            int j  = i & 15;
            int c  = c0 + cc;
            xs[i] = X[((size_t)(b * CH + c)) * N_ + n0 + j] - xbar[c];
        }
        __syncthreads();
#pragma unroll 8
        for (int cc = 0; cc < 32; cc++) {
            float w = Ws[o * 33 + cc];
#pragma unroll
            for (int j = 0; j < 16; j++) acc[j] += w * xs[cc * 16 + j];
        }
        __syncthreads();
    }

#pragma unroll
    for (int j = 0; j < 16; j++) sq[o * 17 + j] = acc[j] * acc[j];
    for (int off = 64; off > 0; off >>= 1) {
        __syncthreads();
        if (o < off) {
#pragma unroll
            for (int j = 0; j < 16; j++) sq[o * 17 + j] += sq[(o + off) * 17 + j];
        }
    }
    __syncthreads();

#pragma unroll
    for (int j = 0; j < 16; j++) {
        float norm = sqrtf(sq[j]) + EPSV;
        OUT[((size_t)(b * CH + o)) * N_ + n0 + j] = acc[j] / norm;
    }
}

// ---------------------------------------------------------------------------
// Pack Q (phi) into m16n8k16 A-frag order, f16 hi + f16 lo.
// Frag (ks in 8, wt in 8, lane): a0=(r=16wt+g, c=16ks+2l..+1), a1=rows+8,
// a2=cols+8, a3=both+8.  grid (32, BATCH), 256 threads, dyn smem 67584B.
// ---------------------------------------------------------------------------
__global__ void k_packQ() {
    extern __shared__ float Qs[];   // [c][r] stride 132
    int blk = blockIdx.x, b = blockIdx.y;
    int n0 = blk * 128;

    for (int i = threadIdx.x; i < 16384; i += 256) {
        int c = i >> 7, r = i & 127;
        Qs[c * 132 + r] = g_phi[((size_t)(b * CH + c)) * N_ + n0 + r];
    }
    __syncthreads();

    uint4* dst = g_Qpk + ((size_t)(b * 32 + blk)) * 4096;
    for (int o = threadIdx.x; o < 2048; o += 256) {
        int lane = o & 31, wt = (o >> 5) & 7, ks = o >> 8;
        int g = lane >> 2, l = lane & 3;
        int r = 16 * wt + g, c = 16 * ks + 2 * l;
        float q00 = Qs[c * 132 + r],           q01 = Qs[(c + 1) * 132 + r];
        float q10 = Qs[c * 132 + r + 8],       q11 = Qs[(c + 1) * 132 + r + 8];
        float q20 = Qs[(c + 8) * 132 + r],     q21 = Qs[(c + 9) * 132 + r];
        float q30 = Qs[(c + 8) * 132 + r + 8], q31 = Qs[(c + 9) * 132 + r + 8];
        uint4 hi, lo;
        hi.x = pack_hi(q00, q01); lo.x = pack_lo(q00, q01);
        hi.y = pack_hi(q10, q11); lo.y = pack_lo(q10, q11);
        hi.z = pack_hi(q20, q21); lo.z = pack_lo(q20, q21);
        hi.w = pack_hi(q30, q31); lo.w = pack_lo(q30, q31);
        dst[o] = hi;
        dst[2048 + o] = lo;
    }
}

// ---------------------------------------------------------------------------
// Pack K (theta) into m16n8k16 B-frag order, uint4 = (b0h,b1h,b0l,b1l).
// ---------------------------------------------------------------------------
__global__ void k_packK() {
    __shared__ float Ks[128 * 68];  // [c][m]
    int kb = blockIdx.x, b = blockIdx.y;
    int m0 = kb * 64;

    for (int i = threadIdx.x; i < 8192; i += 256) {
        int c = i >> 6, m = i & 63;
        Ks[c * 68 + m] = g_theta[((size_t)(b * CH + c)) * N_ + m0 + m];
    }
    __syncthreads();

    uint4* dst = g_Kpk + ((size_t)(b * 64 + kb)) * 2048;
    for (int o = threadIdx.x; o < 2048; o += 256) {
        int lane = o & 31, nt = (o >> 5) & 7, ks = o >> 8;
        int g = lane >> 2, l = lane & 3;
        int c = 16 * ks + 2 * l, m = 8 * nt + g;
        float k00 = Ks[c * 68 + m],       k01 = Ks[(c + 1) * 68 + m];
        float k10 = Ks[(c + 8) * 68 + m], k11 = Ks[(c + 9) * 68 + m];
        uint4 outv;
        outv.x = pack_hi(k00, k01);
        outv.y = pack_hi(k10, k11);
        outv.z = pack_lo(k00, k01);
        outv.w = pack_lo(k10, k11);
        dst[o] = outv;
    }
}

// ---------------------------------------------------------------------------
// Pack V (rs) into m16n8k16 B-frag order, f16 hi + f16 lo.
// ---------------------------------------------------------------------------
__global__ void k_packV(const float* __restrict__ rs) {
    __shared__ float Vt[128 * 68];
    int kb = blockIdx.x, b = blockIdx.y;
    int m0 = kb * 64;

    for (int i = threadIdx.x; i < 2048; i += 256) {
        int c = i >> 4, mq = (i & 15) << 2;
        float4 v = *(const float4*)(rs + ((size_t)(b * CH + c)) * N_ + m0 + mq);
        *(float4*)(Vt + c * 68 + mq) = v;
    }
    __syncthreads();

    uint4* dst = g_Vpk + ((size_t)(b * 64 + kb)) * 2048;
    for (int o = threadIdx.x; o < 2048; o += 256) {
        int lane = o & 31, ct = (o >> 5) & 15, kt = o >> 9;
        int g = lane >> 2, l = lane & 3;
        int c = 8 * ct + g;
        int m = 16 * kt + 2 * l;
        float v0 = Vt[c * 68 + m],     v1 = Vt[c * 68 + m + 1];
        float v8 = Vt[c * 68 + m + 8], v9 = Vt[c * 68 + m + 9];
        uint4 outv;
        outv.x = pack_hi(v0, v1);
        outv.y = pack_hi(v8, v9);
        outv.z = pack_lo(v0, v1);
        outv.w = pack_lo(v8, v9);
        dst[o] = outv;
    }
}

// ---------------------------------------------------------------------------
// K2: flash attention v6. 512 threads = 16 warps.
// Warp w: wt = w&7 owns rows 16wt..+15; grp = w>>3 owns keys [32*grp, +32)
// of each 64-key tile. S: 3x f16 m16n8k16. PV: 3x f16 m16n8k16.
// K/V double-buffered via cp.async. Final cross-group flash merge via smem.
// ---------------------------------------------------------------------------
__global__ void __launch_bounds__(512, 1)
k_attn(float* __restrict__ out) {
    extern __shared__ float sm[];
    uint4* Qf = (uint4*)sm;                  // 4096 uint4: [0,2048) hi, [2048,4096) lo

    int b    = blockIdx.y;
    int n0   = blockIdx.x << 7;
    int tid  = threadIdx.x;
    int lane = tid & 31, w = tid >> 5;
    int wt = w & 7, grp = w >> 3;
    int ntb = grp << 2;                      // nt base
    int g = lane >> 2, l = lane & 3;

    // load persistent Q fragments
    {
        const uint4* qsrc = g_Qpk + ((size_t)(b * 32 + blockIdx.x)) * 4096;
        for (int i = tid; i < 4096; i += 512) Qf[i] = qsrc[i];
    }

    // prologue: async load tile 0 into buffer 0
    {
        uint4* bd = (uint4*)(sm + 16384);
        const uint4* ksrc = g_Kpk + ((size_t)(b * 64 + 0)) * 2048;
        for (int i = tid; i < 2048; i += 512) cpasync16(bd + i, ksrc + i);
        const uint4* vsrc = g_Vpk + ((size_t)(b * 64 + 0)) * 2048;
        for (int i = tid; i < 2048; i += 512) cpasync16(bd + 2048 + i, vsrc + i);
        asm volatile("cp.async.commit_group;\n" ::);
    }

    float O[16][4];
#pragma unroll
    for (int ct = 0; ct < 16; ct++)
#pragma unroll
        for (int j = 0; j < 4; j++) O[ct][j] = 0.f;
    float mi[2] = {-INFINITY, -INFINITY};
    float li[2] = {0.f, 0.f};

    for (int kb = 0; kb < 64; kb++) {
        int cur = kb & 1;
        uint4* Kbuf = (uint4*)(sm + 16384 + cur * 16384);
        uint4* Vbuf = Kbuf + 2048;

        if (kb < 63) {
            uint4* bd = (uint4*)(sm + 16384 + (1 - cur) * 16384);
            const uint4* ksrc = g_Kpk + ((size_t)(b * 64 + kb + 1)) * 2048;
            for (int i = tid; i < 2048; i += 512) cpasync16(bd + i, ksrc + i);
            const uint4* vsrc = g_Vpk + ((size_t)(b * 64 + kb + 1)) * 2048;
            for (int i = tid; i < 2048; i += 512) cpasync16(bd + 2048 + i, vsrc + i);
            asm volatile("cp.async.commit_group;\n" ::);
            asm volatile("cp.async.wait_group 1;\n" ::);
        } else {
            asm volatile("cp.async.wait_group 0;\n" ::);
        }
        __syncthreads();

        // ---- S = Q^T K over this group's 32 keys : 3x f16 mma ----
        float S[4][4];
#pragma unroll
        for (int nt = 0; nt < 4; nt++)
#pragma unroll
            for (int j = 0; j < 4; j++) S[nt][j] = 0.f;

#pragma unroll
        for (int ks = 0; ks < 8; ks++) {
            int qi = (ks * 8 + wt) * 32 + lane;
            uint4 qh = Qf[qi];
            uint4 ql = Qf[2048 + qi];
#pragma unroll
            for (int nt4 = 0; nt4 < 4; nt4++) {
                uint4 kf = Kbuf[(ks * 8 + ntb + nt4) * 32 + lane];
                mma_f16(S[nt4], qh.x, qh.y, qh.z, qh.w, kf.x, kf.y);
                mma_f16(S[nt4], ql.x, ql.y, ql.z, ql.w, kf.x, kf.y);
                mma_f16(S[nt4], qh.x, qh.y, qh.z, qh.w, kf.z, kf.w);
            }
        }

        // ---- warp-local online softmax over 32 keys; P overwrites S ----
#pragma unroll
        for (int hb = 0; hb < 2; hb++) {
            float vmax = -INFINITY;
#pragma unroll
            for (int nt = 0; nt < 4; nt++)
                vmax = fmaxf(vmax, fmaxf(S[nt][2 * hb], S[nt][2 * hb + 1]));
            vmax = fmaxf(vmax, __shfl_xor_sync(0xffffffffu, vmax, 1));
            vmax = fmaxf(vmax, __shfl_xor_sync(0xffffffffu, vmax, 2));
            float mnew  = fmaxf(mi[hb], vmax);
            float alpha = exp2f((mi[hb] - mnew) * SCALE2);
            mi[hb] = mnew;

            float rs_ = 0.f;
#pragma unroll
            for (int nt = 0; nt < 4; nt++) {
                float p0 = exp2f((S[nt][2 * hb]     - mnew) * SCALE2);
                float p1 = exp2f((S[nt][2 * hb + 1] - mnew) * SCALE2);
                S[nt][2 * hb]     = p0;
                S[nt][2 * hb + 1] = p1;
                rs_ += p0 + p1;
            }
            rs_ += __shfl_xor_sync(0xffffffffu, rs_, 1);
            rs_ += __shfl_xor_sync(0xffffffffu, rs_, 2);
            li[hb] = li[hb] * alpha + rs_;

#pragma unroll
            for (int ct = 0; ct < 16; ct++) {
                O[ct][2 * hb]     *= alpha;
                O[ct][2 * hb + 1] *= alpha;
            }
        }

        // ---- PV over this group's 2 kt blocks : 3x f16 mma ----
#pragma unroll
        for (int kt2 = 0; kt2 < 2; kt2++) {
            unsigned int Pha[4], Pla[4];
#pragma unroll
            for (int hf2 = 0; hf2 < 2; hf2++) {
                int nt = 2 * kt2 + hf2;
#pragma unroll
                for (int hb = 0; hb < 2; hb++) {
                    float p0 = S[nt][2 * hb], p1 = S[nt][2 * hb + 1];
                    Pha[hf2 * 2 + hb] = pack_hi(p0, p1);
                    Pla[hf2 * 2 + hb] = pack_lo(p0, p1);
                }
            }
            int kt = 2 * grp + kt2;
#pragma unroll
            for (int ct = 0; ct < 16; ct++) {
                uint4 vf = Vbuf[(kt * 16 + ct) * 32 + lane];
                mma_f16(O[ct], Pha[0], Pha[1], Pha[2], Pha[3], vf.x, vf.y);
                mma_f16(O[ct], Pla[0], Pla[1], Pla[2], Pla[3], vf.x, vf.y);
                mma_f16(O[ct], Pha[0], Pha[1], Pha[2], Pha[3], vf.z, vf.w);
            }
        }
        __syncthreads();
    }

    // ---- cross-group flash merge via smem (aliases buffers) ----
    float* MG = sm + 16384;   // 68 * 512 floats
    if (grp == 1) {
        int slot = tid - 256;
#pragma unroll
        for (int ct = 0; ct < 16; ct++)
#pragma unroll
            for (int j = 0; j < 4; j++)
                MG[(ct * 4 + j) * 512 + slot] = O[ct][j];
#pragma unroll
        for (int hb = 0; hb < 2; hb++) {
            MG[(64 + hb) * 512 + slot] = mi[hb];
            MG[(66 + hb) * 512 + slot] = li[hb];
        }
    }
    __syncthreads();

    if (grp == 0) {
        float* yout = out;
        float* loc  = out + (size_t)BATCH * CH * N_;
#pragma unroll
        for (int hb = 0; hb < 2; hb++) {
            float m1 = MG[(64 + hb) * 512 + tid];
            float l1 = MG[(66 + hb) * 512 + tid];
            float m  = fmaxf(mi[hb], m1);
            float a0 = exp2f((mi[hb] - m) * SCALE2);
            float a1 = exp2f((m1 - m) * SCALE2);
            float lt = li[hb] * a0 + l1 * a1;
            float inv = 1.0f / lt;
            float sc  = m * inv;
            int   r   = n0 + 16 * wt + g + 8 * hb;
#pragma unroll
            for (int ct = 0; ct < 16; ct++) {
                float o0 = O[ct][2 * hb]     * a0 + MG[(ct * 4 + 2 * hb) * 512 + tid]     * a1;
                float o1 = O[ct][2 * hb + 1] * a0 + MG[(ct * 4 + 2 * hb + 1) * 512 + tid] * a1;
                int c0 = 8 * ct + 2 * l;
                yout[((size_t)(b * CH + c0)) * N_ + r]     = o0 * sc;
                yout[((size_t)(b * CH + c0 + 1)) * N_ + r] = o1 * sc;
            }
            if (l == 0) loc[(size_t)b * N_ + r] = inv;
        }
    }
}

// ---------------------------------------------------------------------------
extern "C" void kernel_launch(void* const* d_in, const int* in_sizes, int n_in,
                              void* d_out, int out_size) {
    const float* m_in = (const float*)d_in[0];
    const float* rs   = (const float*)d_in[1];
    const float* thw  = (const float*)d_in[2];
    const float* phw  = (const float*)d_in[4];
    float* out = (float*)d_out;

    k_means<<<1024, 256>>>(m_in, rs);
    k_proj<<<dim3(N_ / 16, BATCH, 2), 128>>>(m_in, rs, thw, phw);

    cudaFuncSetAttribute(k_packQ, cudaFuncAttributeMaxDynamicSharedMemorySize, 132 * 128 * 4);
    k_packQ<<<dim3(32, BATCH), 256, 132 * 128 * 4>>>();
    k_packK<<<dim3(64, BATCH), 256>>>();
    k_packV<<<dim3(64, BATCH), 256>>>(rs);

    size_t smem = (size_t)51200 * sizeof(float);   // 200 KB
    cudaFuncSetAttribute(k_attn, cudaFuncAttributeMaxDynamicSharedMemorySize, (int)smem);
    k_attn<<<dim3(N_ / 128, BATCH), 512, smem>>>(out);
}